// round 11
// baseline (speedup 1.0000x reference)
#include <cuda_runtime.h>
#include <cuda_bf16.h>
#include <cstdint>

#define PLEN  1000
#define QLEN  100
#define BATCH 128
#define DIN   512
#define HID   256
#define H2    512
#define NBLK  128
#define NTHR  256

// ---------------- device scratch (static __device__ allocation) ----------------
__device__ float g_Qp[(size_t)QLEN * BATCH * HID];   // 13.1 MB  [q*B+b, h]
__device__ float g_Pp[(size_t)PLEN * BATCH * HID];   // 131  MB  [p*B+b, h]
__device__ float g_prev[BATCH * HID];
__device__ float g_lh[BATCH * HID];
__device__ float g_utct[BATCH * H2];
__device__ float g_x[BATCH * H2];
__device__ unsigned g_cnt;   // running arrival ticket (never reset; wraps mod 2^32, 128 | 2^32)
__device__ unsigned g_gen;   // generation; monotonically grows across graph replays

// ---------------- helpers ----------------
__device__ __forceinline__ float fast_sig(float x) {
    return __fdividef(1.f, 1.f + __expf(-x));
}
__device__ __forceinline__ float fast_tanh(float x) {
    float e = __expf(2.f * x);
    return 1.f - __fdividef(2.f, e + 1.f);
}

// Ticket grid barrier. target is an absolute generation (base + k), where base
// is read by every thread at kernel entry BEFORE any CTA can release barrier 1
// (release requires all 128 arrivals), so replays are self-consistent with no reset.
__device__ __forceinline__ void grid_bar(unsigned target) {
    __syncthreads();
    if (threadIdx.x == 0) {
        __threadfence();
        unsigned a = atomicAdd(&g_cnt, 1u) + 1u;
        if ((a & (NBLK - 1u)) == 0u) {
            *(volatile unsigned*)&g_gen = target;       // release
        } else {
            while ((int)(*(volatile unsigned*)&g_gen - target) < 0) { }
            __threadfence();                            // acquire
        }
    }
    __syncthreads();
}

// Weight-stationary dot: CTA owns R weight rows (SMEM, row-major over K).
// Thread (bp = tid>>2, ks = tid&3) accumulates batches (2bp, 2bp+1) over the
// ks-th quarter of K; full sums land in ALL ks lanes via shfl butterfly.
// Activation loads are __ldcg (cross-CTA coherent), 64B-contiguous per 4-lane group.
template <int R, int K>
__device__ __forceinline__ void ws_dot(const float* __restrict__ act,
                                       const float* __restrict__ sw,
                                       int b0, int ks, float acc[R][2]) {
#pragma unroll
    for (int r = 0; r < R; r++) { acc[r][0] = 0.f; acc[r][1] = 0.f; }
    const float* a0p = act + (size_t)b0 * K;
    const float* a1p = a0p + K;
#pragma unroll 4
    for (int m = 0; m < K / 16; m++) {
        int k0 = m * 16 + ks * 4;
        float4 a0 = __ldcg((const float4*)(a0p + k0));
        float4 a1 = __ldcg((const float4*)(a1p + k0));
#pragma unroll
        for (int r = 0; r < R; r++) {
            float4 w = *(const float4*)(sw + r * K + k0);
            acc[r][0] = fmaf(w.x, a0.x, acc[r][0]);
            acc[r][0] = fmaf(w.y, a0.y, acc[r][0]);
            acc[r][0] = fmaf(w.z, a0.z, acc[r][0]);
            acc[r][0] = fmaf(w.w, a0.w, acc[r][0]);
            acc[r][1] = fmaf(w.x, a1.x, acc[r][1]);
            acc[r][1] = fmaf(w.y, a1.y, acc[r][1]);
            acc[r][1] = fmaf(w.z, a1.z, acc[r][1]);
            acc[r][1] = fmaf(w.w, a1.w, acc[r][1]);
        }
    }
#pragma unroll
    for (int r = 0; r < R; r++) {
#pragma unroll
        for (int j = 0; j < 2; j++) {
            float v = acc[r][j];
            v += __shfl_xor_sync(0xffffffffu, v, 1);
            v += __shfl_xor_sync(0xffffffffu, v, 2);
            acc[r][j] = v;
        }
    }
}

// ---------------- precompute SGEMM: C[M,256] = A[M,512] @ W[256,512]^T --------
// which = 0 -> C = g_Qp, which = 1 -> C = g_Pp. 64x64 tiles, K-tile 16.
__global__ void __launch_bounds__(256) gemm_nt_kernel(
    const float* __restrict__ A, const float* __restrict__ W, int which) {
    float* __restrict__ C = which ? g_Pp : g_Qp;
    const int N = HID, K = DIN;
    __shared__ __align__(16) float As[16][68];
    __shared__ __align__(16) float Bs[16][68];
    int tid = threadIdx.x;
    int row0 = blockIdx.y * 64;
    int col0 = blockIdx.x * 64;
    int lm = tid >> 2;
    int lk = (tid & 3) << 2;
    int ty = tid >> 4;
    int tx = tid & 15;
    float acc[4][4] = {};
    const float* Ap = A + (size_t)(row0 + lm) * K + lk;
    const float* Wp = W + (size_t)(col0 + lm) * K + lk;
    for (int kt = 0; kt < K; kt += 16) {
        float4 a = *(const float4*)(Ap + kt);
        float4 b = *(const float4*)(Wp + kt);
        As[lk + 0][lm] = a.x; As[lk + 1][lm] = a.y; As[lk + 2][lm] = a.z; As[lk + 3][lm] = a.w;
        Bs[lk + 0][lm] = b.x; Bs[lk + 1][lm] = b.y; Bs[lk + 2][lm] = b.z; Bs[lk + 3][lm] = b.w;
        __syncthreads();
#pragma unroll
        for (int k = 0; k < 16; k++) {
            float4 av = *(const float4*)(&As[k][ty << 2]);
            float4 bv = *(const float4*)(&Bs[k][tx << 2]);
            float ar[4] = {av.x, av.y, av.z, av.w};
            float br[4] = {bv.x, bv.y, bv.z, bv.w};
#pragma unroll
            for (int mi = 0; mi < 4; mi++)
#pragma unroll
                for (int ni = 0; ni < 4; ni++)
                    acc[mi][ni] = fmaf(ar[mi], br[ni], acc[mi][ni]);
        }
        __syncthreads();
    }
#pragma unroll
    for (int mi = 0; mi < 4; mi++) {
        float4 o = make_float4(acc[mi][0], acc[mi][1], acc[mi][2], acc[mi][3]);
        *(float4*)(C + (size_t)(row0 + (ty << 2) + mi) * N + col0 + (tx << 2)) = o;
    }
}

// ---------------- persistent recurrent kernel ----------------
// SMEM floats: s_qp 25600 | s_w1 2048 | s_w4 2048 | s_w5 3072 | s_vt 256 |
//              s_pi 256 | s_lh 256 | s_logit 128 | s_a 128   => 33792 floats
#define SMEM_FLOATS (25600 + 2048 + 2048 + 3072 + 256 + 256 + 256 + 128 + 128)
#define SMEM_BYTES  (SMEM_FLOATS * 4)

__global__ void __launch_bounds__(NTHR, 1) rnn_persistent(
    const float* __restrict__ vT,
    const float* __restrict__ WvP,
    const float* __restrict__ Wg,
    const float* __restrict__ W_ih,
    const float* __restrict__ W_hh,
    float* __restrict__ out) {
    extern __shared__ float sm[];
    float* s_qp    = sm;                       // [QLEN][HID], this CTA's batch slice
    float* s_w1    = s_qp + QLEN * HID;        // 8 rows x HID  (P1 weights)
    float* s_w4    = s_w1 + 8 * HID;           // 4 rows x H2   (Wg slice)
    float* s_w5    = s_w4 + 4 * H2;            // 6 rows x H2   (W_ih slice)
    float* s_vt    = s_w5 + 6 * H2;
    float* s_pi    = s_vt + HID;
    float* s_lh    = s_pi + HID;               // holds pi + lh during attention
    float* s_logit = s_lh + HID;
    float* s_a     = s_logit + 128;

    const int tid = threadIdx.x;
    const int b = blockIdx.x;   // batch owned for attention phase
    const int c = b;            // weight-shard id (h-dims 2c, 2c+1)

    // read barrier base BEFORE any arrival (safe: barrier-1 release needs all CTAs)
    unsigned tgt = *(volatile unsigned*)&g_gen;

    // ---- one-time SMEM loads ----
    // s_w1 rows: 0,1 = WvP[2c],[2c+1]; 2..7 = W_hh rows {g*256 + 2c + j}, g=0..2
    for (int i = tid; i < 8 * HID; i += NTHR) {
        int r = i / HID, k = i - r * HID;
        const float* src;
        if (r < 2) src = WvP + (size_t)(2 * c + r) * HID;
        else {
            int g = (r - 2) >> 1, j = (r - 2) & 1;
            src = W_hh + (size_t)(g * HID + 2 * c + j) * HID;
        }
        s_w1[i] = src[k];
    }
    for (int i = tid; i < 4 * H2; i += NTHR) {
        int r = i / H2, k = i - r * H2;
        s_w4[i] = Wg[(size_t)(4 * c + r) * H2 + k];
    }
    // s_w5 rows: {g*256 + 2c + j}, g=0..2 (Wir,Wiz,Win), j=0,1
    for (int i = tid; i < 6 * H2; i += NTHR) {
        int r = i / H2, k = i - r * H2;
        int g = r >> 1, j = r & 1;
        s_w5[i] = W_ih[(size_t)(g * HID + 2 * c + j) * H2 + k];
    }
    for (int i = tid; i < HID; i += NTHR) s_vt[i] = vT[i];
    for (int q = 0; q < QLEN; q++)
        s_qp[q * HID + tid] = g_Qp[((size_t)q * BATCH + b) * HID + tid];
    // zero this CTA's owned dims of prev across all batches
    if (tid < BATCH) {
        g_prev[tid * HID + 2 * c]     = 0.f;
        g_prev[tid * HID + 2 * c + 1] = 0.f;
    }
    grid_bar(++tgt);  // prev zeroed + prior-kernel outputs coherently visible

    const int bp = tid >> 2;
    const int ks = tid & 3;
    const int b0 = bp * 2;
    const int wrp = tid >> 5;
    const int lane = tid & 31;

#pragma unroll 1
    for (int step = 0; step < PLEN; step++) {
        float hhr[2][2], hhz[2][2], hhn[2][2];

        // ---- P1: lh dims {2c,2c+1} -> g_lh ; hh gate-triples kept in registers
        {
            float acc[8][2];
            ws_dot<8, HID>(g_prev, s_w1, b0, ks, acc);
#pragma unroll
            for (int j = 0; j < 2; j++)
#pragma unroll
                for (int jb = 0; jb < 2; jb++) {
                    hhr[j][jb] = acc[2 + j][jb];
                    hhz[j][jb] = acc[4 + j][jb];
                    hhn[j][jb] = acc[6 + j][jb];
                }
            if (ks == 0) {
#pragma unroll
                for (int j = 0; j < 2; j++) {
                    g_lh[(b0)     * HID + 2 * c + j] = acc[j][0];
                    g_lh[(b0 + 1) * HID + 2 * c + j] = acc[j][1];
                }
            }
        }
        grid_bar(++tgt);  // bar A: lh visible

        // ---- P2/P3: attention for batch b -> utct
        {
            float piv = g_Pp[((size_t)step * BATCH + b) * HID + tid];
            s_pi[tid] = piv;
            s_lh[tid] = piv + __ldcg(&g_lh[b * HID + tid]);   // pi + lh
            __syncthreads();
            for (int q = wrp; q < QLEN; q += 8) {
                const float* qp = s_qp + q * HID;
                float sum = 0.f;
#pragma unroll
                for (int ii = 0; ii < 8; ii++) {
                    int h = lane + (ii << 5);
                    float t = fast_tanh(s_lh[h] + qp[h]);
                    sum = fmaf(s_vt[h], t, sum);
                }
#pragma unroll
                for (int off = 16; off; off >>= 1)
                    sum += __shfl_xor_sync(0xffffffffu, sum, off);
                if (lane == 0) s_logit[q] = sum;
            }
            __syncthreads();
            if (wrp == 0) {
                float mx = -3.0e38f;
                for (int q = lane; q < QLEN; q += 32) mx = fmaxf(mx, s_logit[q]);
#pragma unroll
                for (int off = 16; off; off >>= 1)
                    mx = fmaxf(mx, __shfl_xor_sync(0xffffffffu, mx, off));
                float sum = 0.f;
                for (int q = lane; q < QLEN; q += 32) {
                    float e = __expf(s_logit[q] - mx);
                    s_a[q] = e;
                    sum += e;
                }
#pragma unroll
                for (int off = 16; off; off >>= 1)
                    sum += __shfl_xor_sync(0xffffffffu, sum, off);
                float rinv = __fdividef(1.f, sum);
                for (int q = lane; q < QLEN; q += 32) s_a[q] *= rinv;
            }
            __syncthreads();
            float ct = 0.f;
            const float* qc = s_qp + tid;
#pragma unroll 4
            for (int q = 0; q < QLEN; q++) ct = fmaf(s_a[q], qc[q * HID], ct);
            g_utct[b * H2 + tid]       = s_pi[tid];
            g_utct[b * H2 + HID + tid] = ct;
        }
        grid_bar(++tgt);  // bar B: utct visible

        // ---- P4: gated projection rows {4c..4c+4): x = utct * sig(utct @ Wg^T)
        {
            float acc[4][2];
            ws_dot<4, H2>(g_utct, s_w4, b0, ks, acc);
            if (ks == 0) {
                int j0 = c * 4;
#pragma unroll
                for (int r = 0; r < 4; r++)
#pragma unroll
                    for (int jb = 0; jb < 2; jb++) {
                        float u = __ldcg(&g_utct[(b0 + jb) * H2 + j0 + r]);
                        g_x[(b0 + jb) * H2 + j0 + r] = u * fast_sig(acc[r][jb]);
                    }
            }
        }
        grid_bar(++tgt);  // bar C: x visible

        // ---- P5 + update: gi = x @ W_ih^T (owned rows) fused with GRU update
        {
            float acc[6][2];
            ws_dot<6, H2>(g_x, s_w5, b0, ks, acc);
            if (ks == 0) {
#pragma unroll
                for (int j = 0; j < 2; j++)
#pragma unroll
                    for (int jb = 0; jb < 2; jb++) {
                        int d = 2 * c + j;
                        int bb = b0 + jb;
                        float r = fast_sig(acc[j][jb]     + hhr[j][jb]);
                        float z = fast_sig(acc[2 + j][jb] + hhz[j][jb]);
                        float n = fast_tanh(acc[4 + j][jb] + r * hhn[j][jb]);
                        float pv = __ldcg(&g_prev[bb * HID + d]);
                        float h = n + z * (pv - n);
                        g_prev[bb * HID + d] = h;
                        out[((size_t)step * BATCH + bb) * HID + d] = h;
                    }
            }
        }
        grid_bar(++tgt);  // bar D: prev visible for next P1
    }
}

// ---------------- launch ----------------
extern "C" void kernel_launch(void* const* d_in, const int* in_sizes, int n_in,
                              void* d_out, int out_size) {
    const float* passage_repr  = (const float*)d_in[0];   // [1000,128,512]
    const float* question_repr = (const float*)d_in[1];   // [100,128,512]
    // d_in[2], d_in[3]: masks, unused (faithful to reference)
    const float* vT   = (const float*)d_in[4];            // [256]
    const float* WuQ  = (const float*)d_in[5];            // [256,512]
    const float* WuP  = (const float*)d_in[6];            // [256,512]
    const float* WvP  = (const float*)d_in[7];            // [256,256]
    const float* Wg   = (const float*)d_in[8];            // [512,512]
    const float* W_ih = (const float*)d_in[9];            // [768,512]
    const float* W_hh = (const float*)d_in[10];           // [768,256]
    float* out = (float*)d_out;

    // Qp = question_repr @ WuQ^T : M = 100*128 = 12800
    gemm_nt_kernel<<<dim3(HID / 64, (QLEN * BATCH) / 64), 256>>>(question_repr, WuQ, 0);
    // Pp = passage_repr @ WuP^T : M = 1000*128 = 128000
    gemm_nt_kernel<<<dim3(HID / 64, (PLEN * BATCH) / 64), 256>>>(passage_repr, WuP, 1);

    cudaFuncSetAttribute(rnn_persistent,
                         cudaFuncAttributeMaxDynamicSharedMemorySize, SMEM_BYTES);
    rnn_persistent<<<NBLK, NTHR, SMEM_BYTES>>>(vT, WvP, Wg, W_ih, W_hh, out);
}

// round 16
// speedup vs baseline: 1.0153x; 1.0153x over previous
#include <cuda_runtime.h>
#include <cuda_bf16.h>
#include <cstdint>

#define PLEN  1000
#define QLEN  100
#define BATCH 128
#define DIN   512
#define HID   256
#define H2    512
#define NBLK  128
#define NTHR  256

typedef unsigned long long u64;

// ---------------- device scratch (static __device__ allocation) ----------------
__device__ float g_Qp[(size_t)QLEN * BATCH * HID];   // 13.1 MB  [q*B+b, h]
__device__ float g_Pp[(size_t)PLEN * BATCH * HID];   // 131  MB  [p*B+b, h]
__device__ float g_prev[BATCH * HID];
__device__ float g_lh[BATCH * HID];
__device__ float g_utct[BATCH * H2];
__device__ float g_x[BATCH * H2];
__device__ unsigned g_cnt;   // running arrival ticket (never reset)
__device__ unsigned g_gen;   // generation; monotonically grows across graph replays

// ---------------- helpers ----------------
__device__ __forceinline__ float fast_sig(float x) {
    return __fdividef(1.f, 1.f + __expf(-x));
}
__device__ __forceinline__ float fast_tanh(float x) {
    float e = __expf(2.f * x);
    return 1.f - __fdividef(2.f, e + 1.f);
}

// packed 2-wide fp32 FMA (Blackwell f32x2; ptxas never emits it from C++)
__device__ __forceinline__ u64 ffma2(u64 a, u64 b, u64 c) {
    u64 d;
    asm("fma.rn.f32x2 %0, %1, %2, %3;" : "=l"(d) : "l"(a), "l"(b), "l"(c));
    return d;
}
__device__ __forceinline__ u64 splat2(float a) {
    u64 d;
    asm("mov.b64 %0, {%1, %1};" : "=l"(d) : "f"(a));
    return d;
}
__device__ __forceinline__ float pair_sum(u64 v) {
    float lo = __uint_as_float((unsigned)(v & 0xffffffffull));
    float hi = __uint_as_float((unsigned)(v >> 32));
    return lo + hi;
}
__device__ __forceinline__ u64 d2u(double d) { return (u64)__double_as_longlong(d); }

// Ticket grid barrier; base generation read at kernel entry (before any CTA can
// release barrier 1, since release needs all 128 arrivals) -> replay-safe, no reset.
__device__ __forceinline__ void grid_bar(unsigned target) {
    __syncthreads();
    if (threadIdx.x == 0) {
        __threadfence();
        unsigned a = atomicAdd(&g_cnt, 1u) + 1u;
        if ((a & (NBLK - 1u)) == 0u) {
            *(volatile unsigned*)&g_gen = target;       // release
        } else {
            while ((int)(*(volatile unsigned*)&g_gen - target) < 0) { }
            __threadfence();                            // acquire
        }
    }
    __syncthreads();
}

// Weight-stationary dot with f32x2 packing along K.
// CTA owns R weight rows (SMEM, row-major over K). Thread (bp = tid>>2, ks = tid&3)
// accumulates batches (2bp, 2bp+1) over the ks-th quarter of K; full sums land in
// all ks lanes via shfl butterfly. Activation loads are __ldcg (cross-CTA coherent).
template <int R, int K>
__device__ __forceinline__ void ws_dot(const float* __restrict__ act,
                                       const float* __restrict__ sw,
                                       int b0, int ks, float acc[R][2]) {
    u64 accp[R][2];
#pragma unroll
    for (int r = 0; r < R; r++) { accp[r][0] = 0ull; accp[r][1] = 0ull; }
    const float* a0p = act + (size_t)b0 * K;
    const float* a1p = a0p + K;
#pragma unroll 4
    for (int m = 0; m < K / 16; m++) {
        int k0 = m * 16 + ks * 4;
        double2 a0d = __ldcg((const double2*)(a0p + k0));   // {k0,k0+1},{k0+2,k0+3}
        double2 a1d = __ldcg((const double2*)(a1p + k0));
        u64 a0x = d2u(a0d.x), a0y = d2u(a0d.y);
        u64 a1x = d2u(a1d.x), a1y = d2u(a1d.y);
#pragma unroll
        for (int r = 0; r < R; r++) {
            const double2 wd = *(const double2*)(sw + r * K + k0);
            u64 wx = d2u(wd.x), wy = d2u(wd.y);
            accp[r][0] = ffma2(wx, a0x, accp[r][0]);
            accp[r][0] = ffma2(wy, a0y, accp[r][0]);
            accp[r][1] = ffma2(wx, a1x, accp[r][1]);
            accp[r][1] = ffma2(wy, a1y, accp[r][1]);
        }
    }
#pragma unroll
    for (int r = 0; r < R; r++) {
#pragma unroll
        for (int j = 0; j < 2; j++) {
            float v = pair_sum(accp[r][j]);
            v += __shfl_xor_sync(0xffffffffu, v, 1);
            v += __shfl_xor_sync(0xffffffffu, v, 2);
            acc[r][j] = v;
        }
    }
}

// ---------------- precompute SGEMM: C[M,256] = A[M,512] @ W[256,512]^T --------
// which = 0 -> C = g_Qp, which = 1 -> C = g_Pp. 64x64 tiles, K-tile 16, f32x2 core.
__global__ void __launch_bounds__(256) gemm_nt_kernel(
    const float* __restrict__ A, const float* __restrict__ W, int which) {
    float* __restrict__ C = which ? g_Pp : g_Qp;
    const int N = HID, K = DIN;
    __shared__ __align__(16) float As[16][68];
    __shared__ __align__(16) float Bs[16][68];
    int tid = threadIdx.x;
    int row0 = blockIdx.y * 64;
    int col0 = blockIdx.x * 64;
    int lm = tid >> 2;
    int lk = (tid & 3) << 2;
    int ty = tid >> 4;
    int tx = tid & 15;
    u64 acc2[4][2];
#pragma unroll
    for (int mi = 0; mi < 4; mi++) { acc2[mi][0] = 0ull; acc2[mi][1] = 0ull; }
    const float* Ap = A + (size_t)(row0 + lm) * K + lk;
    const float* Wp = W + (size_t)(col0 + lm) * K + lk;
    for (int kt = 0; kt < K; kt += 16) {
        float4 a = *(const float4*)(Ap + kt);
        float4 b = *(const float4*)(Wp + kt);
        As[lk + 0][lm] = a.x; As[lk + 1][lm] = a.y; As[lk + 2][lm] = a.z; As[lk + 3][lm] = a.w;
        Bs[lk + 0][lm] = b.x; Bs[lk + 1][lm] = b.y; Bs[lk + 2][lm] = b.z; Bs[lk + 3][lm] = b.w;
        __syncthreads();
#pragma unroll
        for (int k = 0; k < 16; k++) {
            float4 av = *(const float4*)(&As[k][ty << 2]);
            double2 bvd = *(const double2*)(&Bs[k][tx << 2]);   // 16B-aligned (row 272B)
            u64 b01 = d2u(bvd.x), b23 = d2u(bvd.y);
            float ar[4] = {av.x, av.y, av.z, av.w};
#pragma unroll
            for (int mi = 0; mi < 4; mi++) {
                u64 asplat = splat2(ar[mi]);
                acc2[mi][0] = ffma2(asplat, b01, acc2[mi][0]);
                acc2[mi][1] = ffma2(asplat, b23, acc2[mi][1]);
            }
        }
        __syncthreads();
    }
#pragma unroll
    for (int mi = 0; mi < 4; mi++) {
        float4 o;
        o.x = __uint_as_float((unsigned)(acc2[mi][0] & 0xffffffffull));
        o.y = __uint_as_float((unsigned)(acc2[mi][0] >> 32));
        o.z = __uint_as_float((unsigned)(acc2[mi][1] & 0xffffffffull));
        o.w = __uint_as_float((unsigned)(acc2[mi][1] >> 32));
        *(float4*)(C + (size_t)(row0 + (ty << 2) + mi) * N + col0 + (tx << 2)) = o;
    }
}

// ---------------- persistent recurrent kernel ----------------
// SMEM floats: s_qp 25600 | s_w1 2048 | s_w4 2048 | s_w5 3072 | s_vt 256 |
//              s_pi 256 | s_lh 256 | s_logit 128 | s_a 128   => 33792 floats
#define SMEM_FLOATS (25600 + 2048 + 2048 + 3072 + 256 + 256 + 256 + 128 + 128)
#define SMEM_BYTES  (SMEM_FLOATS * 4)

__global__ void __launch_bounds__(NTHR, 1) rnn_persistent(
    const float* __restrict__ vT,
    const float* __restrict__ WvP,
    const float* __restrict__ Wg,
    const float* __restrict__ W_ih,
    const float* __restrict__ W_hh,
    float* __restrict__ out) {
    extern __shared__ float sm[];
    float* s_qp    = sm;                       // [QLEN][HID], this CTA's batch slice
    float* s_w1    = s_qp + QLEN * HID;        // 8 rows x HID  (WvP + W_hh shard)
    float* s_w4    = s_w1 + 8 * HID;           // 4 rows x H2   (Wg shard)
    float* s_w5    = s_w4 + 4 * H2;            // 6 rows x H2   (W_ih shard)
    float* s_vt    = s_w5 + 6 * H2;
    float* s_pi    = s_vt + HID;
    float* s_lh    = s_pi + HID;               // pi + lh during attention
    float* s_logit = s_lh + HID;
    float* s_a     = s_logit + 128;

    const int tid = threadIdx.x;
    const int b = blockIdx.x;   // batch owned for attention phase
    const int c = b;            // weight-shard id (h-dims 2c, 2c+1)

    // read barrier base BEFORE any arrival (release of bar 1 needs all CTAs)
    unsigned tgt = *(volatile unsigned*)&g_gen;

    // ---- one-time SMEM loads ----
    // s_w1 rows: 0,1 = WvP[2c],[2c+1]; 2..7 = W_hh rows {g*256 + 2c + j}, g=0..2
    for (int i = tid; i < 8 * HID; i += NTHR) {
        int r = i / HID, k = i - r * HID;
        const float* src;
        if (r < 2) src = WvP + (size_t)(2 * c + r) * HID;
        else {
            int g = (r - 2) >> 1, j = (r - 2) & 1;
            src = W_hh + (size_t)(g * HID + 2 * c + j) * HID;
        }
        s_w1[i] = src[k];
    }
    for (int i = tid; i < 4 * H2; i += NTHR) {
        int r = i / H2, k = i - r * H2;
        s_w4[i] = Wg[(size_t)(4 * c + r) * H2 + k];
    }
    for (int i = tid; i < 6 * H2; i += NTHR) {
        int r = i / H2, k = i - r * H2;
        int g = r >> 1, j = r & 1;
        s_w5[i] = W_ih[(size_t)(g * HID + 2 * c + j) * H2 + k];
    }
    for (int i = tid; i < HID; i += NTHR) s_vt[i] = vT[i];
    for (int q = 0; q < QLEN; q++)
        s_qp[q * HID + tid] = g_Qp[((size_t)q * BATCH + b) * HID + tid];
    if (tid < BATCH) {
        g_prev[tid * HID + 2 * c]     = 0.f;
        g_prev[tid * HID + 2 * c + 1] = 0.f;
    }
    grid_bar(++tgt);  // prev zeroed + prior-kernel outputs coherently visible

    const int bp = tid >> 2;
    const int ks = tid & 3;
    const int b0 = bp * 2;
    const int wrp = tid >> 5;
    const int lane = tid & 31;

#pragma unroll 1
    for (int step = 0; step < PLEN; step++) {
        float hhr[2][2], hhz[2][2], hhn[2][2];

        // ---- P1: lh dims {2c,2c+1} -> g_lh ; hh gate triples kept in registers
        {
            float acc[8][2];
            ws_dot<8, HID>(g_prev, s_w1, b0, ks, acc);
#pragma unroll
            for (int j = 0; j < 2; j++)
#pragma unroll
                for (int jb = 0; jb < 2; jb++) {
                    hhr[j][jb] = acc[2 + j][jb];
                    hhz[j][jb] = acc[4 + j][jb];
                    hhn[j][jb] = acc[6 + j][jb];
                }
            if (ks == 0) {
#pragma unroll
                for (int j = 0; j < 2; j++) {
                    g_lh[(b0)     * HID + 2 * c + j] = acc[j][0];
                    g_lh[(b0 + 1) * HID + 2 * c + j] = acc[j][1];
                }
            }
        }
        grid_bar(++tgt);  // bar A: lh visible

        // ---- P2/P3: attention for batch b -> utct
        {
            float piv = g_Pp[((size_t)step * BATCH + b) * HID + tid];
            s_pi[tid] = piv;
            s_lh[tid] = piv + __ldcg(&g_lh[b * HID + tid]);   // pi + lh
            __syncthreads();
            for (int q = wrp; q < QLEN; q += 8) {
                const float* qp = s_qp + q * HID;
                float sum = 0.f;
#pragma unroll
                for (int ii = 0; ii < 8; ii++) {
                    int h = lane + (ii << 5);
                    float t = fast_tanh(s_lh[h] + qp[h]);
                    sum = fmaf(s_vt[h], t, sum);
                }
#pragma unroll
                for (int off = 16; off; off >>= 1)
                    sum += __shfl_xor_sync(0xffffffffu, sum, off);
                if (lane == 0) s_logit[q] = sum;
            }
            __syncthreads();
            if (wrp == 0) {
                float mx = -3.0e38f;
                for (int q = lane; q < QLEN; q += 32) mx = fmaxf(mx, s_logit[q]);
#pragma unroll
                for (int off = 16; off; off >>= 1)
                    mx = fmaxf(mx, __shfl_xor_sync(0xffffffffu, mx, off));
                float sum = 0.f;
                for (int q = lane; q < QLEN; q += 32) {
                    float e = __expf(s_logit[q] - mx);
                    s_a[q] = e;
                    sum += e;
                }
#pragma unroll
                for (int off = 16; off; off >>= 1)
                    sum += __shfl_xor_sync(0xffffffffu, sum, off);
                float rinv = __fdividef(1.f, sum);
                for (int q = lane; q < QLEN; q += 32) s_a[q] *= rinv;
            }
            __syncthreads();
            float ct = 0.f;
            const float* qc = s_qp + tid;
#pragma unroll 4
            for (int q = 0; q < QLEN; q++) ct = fmaf(s_a[q], qc[q * HID], ct);
            g_utct[b * H2 + tid]       = s_pi[tid];
            g_utct[b * H2 + HID + tid] = ct;
        }
        grid_bar(++tgt);  // bar B: utct visible

        // ---- P4: gated projection rows {4c..4c+4): x = utct * sig(utct @ Wg^T)
        {
            float acc[4][2];
            ws_dot<4, H2>(g_utct, s_w4, b0, ks, acc);
            if (ks == 0) {
                int j0 = c * 4;
#pragma unroll
                for (int r = 0; r < 4; r++)
#pragma unroll
                    for (int jb = 0; jb < 2; jb++) {
                        float u = __ldcg(&g_utct[(b0 + jb) * H2 + j0 + r]);
                        g_x[(b0 + jb) * H2 + j0 + r] = u * fast_sig(acc[r][jb]);
                    }
            }
        }
        grid_bar(++tgt);  // bar C: x visible

        // ---- P5 + update: gi = x @ W_ih^T (owned rows) fused with GRU update
        {
            float acc[6][2];
            ws_dot<6, H2>(g_x, s_w5, b0, ks, acc);
            if (ks == 0) {
#pragma unroll
                for (int j = 0; j < 2; j++)
#pragma unroll
                    for (int jb = 0; jb < 2; jb++) {
                        int d = 2 * c + j;
                        int bb = b0 + jb;
                        float r = fast_sig(acc[j][jb]     + hhr[j][jb]);
                        float z = fast_sig(acc[2 + j][jb] + hhz[j][jb]);
                        float n = fast_tanh(acc[4 + j][jb] + r * hhn[j][jb]);
                        float pv = __ldcg(&g_prev[bb * HID + d]);
                        float h = n + z * (pv - n);
                        g_prev[bb * HID + d] = h;
                        out[((size_t)step * BATCH + bb) * HID + d] = h;
                    }
            }
        }
        grid_bar(++tgt);  // bar D: prev visible for next P1
    }
}

// ---------------- launch ----------------
extern "C" void kernel_launch(void* const* d_in, const int* in_sizes, int n_in,
                              void* d_out, int out_size) {
    const float* passage_repr  = (const float*)d_in[0];   // [1000,128,512]
    const float* question_repr = (const float*)d_in[1];   // [100,128,512]
    // d_in[2], d_in[3]: masks, unused (faithful to reference)
    const float* vT   = (const float*)d_in[4];            // [256]
    const float* WuQ  = (const float*)d_in[5];            // [256,512]
    const float* WuP  = (const float*)d_in[6];            // [256,512]
    const float* WvP  = (const float*)d_in[7];            // [256,256]
    const float* Wg   = (const float*)d_in[8];            // [512,512]
    const float* W_ih = (const float*)d_in[9];            // [768,512]
    const float* W_hh = (const float*)d_in[10];           // [768,256]
    float* out = (float*)d_out;

    // Qp = question_repr @ WuQ^T : M = 100*128 = 12800
    gemm_nt_kernel<<<dim3(HID / 64, (QLEN * BATCH) / 64), 256>>>(question_repr, WuQ, 0);
    // Pp = passage_repr @ WuP^T : M = 1000*128 = 128000
    gemm_nt_kernel<<<dim3(HID / 64, (PLEN * BATCH) / 64), 256>>>(passage_repr, WuP, 1);

    cudaFuncSetAttribute(rnn_persistent,
                         cudaFuncAttributeMaxDynamicSharedMemorySize, SMEM_BYTES);
    rnn_persistent<<<NBLK, NTHR, SMEM_BYTES>>>(vT, WvP, Wg, W_ih, W_hh, out);
}

// round 17
// speedup vs baseline: 1.1730x; 1.1554x over previous
#include <cuda_runtime.h>
#include <cuda_bf16.h>
#include <cstdint>

#define PLEN  1000
#define QLEN  100
#define BATCH 128
#define DIN   512
#define HID   256
#define H2    512
#define NBLK  128
#define NTHR  512

typedef unsigned long long u64;

// ---------------- device scratch (static __device__ allocation) ----------------
__device__ float g_Qp[(size_t)QLEN * BATCH * HID];   // 13.1 MB  [q*B+b, h]
__device__ float g_Pp[(size_t)PLEN * BATCH * HID];   // 131  MB  [p*B+b, h]
__device__ float g_prev[BATCH * HID];
__device__ float g_lh[BATCH * HID];
__device__ float g_utct[BATCH * H2];
__device__ float g_x[BATCH * H2];
__device__ unsigned g_cnt;   // running arrival ticket (never reset)
__device__ unsigned g_gen;   // generation; monotonically grows across graph replays

// ---------------- helpers ----------------
__device__ __forceinline__ float fast_sig(float x) {
    return __fdividef(1.f, 1.f + __expf(-x));
}
__device__ __forceinline__ float fast_tanh(float x) {
    float e = __expf(2.f * x);
    return 1.f - __fdividef(2.f, e + 1.f);
}
__device__ __forceinline__ u64 ffma2(u64 a, u64 b, u64 c) {
    u64 d;
    asm("fma.rn.f32x2 %0, %1, %2, %3;" : "=l"(d) : "l"(a), "l"(b), "l"(c));
    return d;
}
__device__ __forceinline__ float pair_sum(u64 v) {
    float lo = __uint_as_float((unsigned)(v & 0xffffffffull));
    float hi = __uint_as_float((unsigned)(v >> 32));
    return lo + hi;
}
__device__ __forceinline__ u64 d2u(double d) { return (u64)__double_as_longlong(d); }

// Ticket grid barrier; base generation read at kernel entry (before any CTA can
// release barrier 1, since release needs all 128 arrivals) -> replay-safe.
__device__ __forceinline__ void grid_bar(unsigned target) {
    __syncthreads();
    if (threadIdx.x == 0) {
        __threadfence();
        unsigned a = atomicAdd(&g_cnt, 1u) + 1u;
        if ((a & (NBLK - 1u)) == 0u) {
            *(volatile unsigned*)&g_gen = target;       // release
        } else {
            while ((int)(*(volatile unsigned*)&g_gen - target) < 0) { }
            __threadfence();                            // acquire
        }
    }
    __syncthreads();
}

// Weight-stationary dot, f32x2 packed along K, BB batches per thread.
// thread = (bp = tid/KS, ks = tid%KS); bp owns batches [bp*BB, bp*BB+BB);
// ks owns the ks-th 1/KS slice of K. Requires NTHR/KS * BB == BATCH.
// Full sums land in all ks lanes via shfl butterfly (KS power of two <= 32).
template <int R, int K, int BB, int KS>
__device__ __forceinline__ void ws_dot(const float* __restrict__ act,
                                       const float* __restrict__ sw,
                                       int tid, float acc[R][BB]) {
    const int ks = tid & (KS - 1);
    const int b0 = (tid / KS) * BB;
    u64 accp[R][BB];
#pragma unroll
    for (int r = 0; r < R; r++)
#pragma unroll
        for (int jb = 0; jb < BB; jb++) accp[r][jb] = 0ull;
    constexpr int M = K / (4 * KS);
#pragma unroll 2
    for (int m = 0; m < M; m++) {
        int k0 = m * 4 * KS + ks * 4;
        u64 a[BB][2];
#pragma unroll
        for (int jb = 0; jb < BB; jb++) {
            double2 ad = __ldcg((const double2*)(act + (size_t)(b0 + jb) * K + k0));
            a[jb][0] = d2u(ad.x); a[jb][1] = d2u(ad.y);
        }
#pragma unroll
        for (int r = 0; r < R; r++) {
            double2 wd = *(const double2*)(sw + r * K + k0);
            u64 wx = d2u(wd.x), wy = d2u(wd.y);
#pragma unroll
            for (int jb = 0; jb < BB; jb++) {
                accp[r][jb] = ffma2(wx, a[jb][0], accp[r][jb]);
                accp[r][jb] = ffma2(wy, a[jb][1], accp[r][jb]);
            }
        }
    }
#pragma unroll
    for (int r = 0; r < R; r++)
#pragma unroll
        for (int jb = 0; jb < BB; jb++) {
            float v = pair_sum(accp[r][jb]);
#pragma unroll
            for (int off = 1; off < KS; off <<= 1)
                v += __shfl_xor_sync(0xffffffffu, v, off);
            acc[r][jb] = v;
        }
}

// ---------------- precompute SGEMM: C[M,256] = A[M,512] @ W[256,512]^T --------
__global__ void __launch_bounds__(256) gemm_nt_kernel(
    const float* __restrict__ A, const float* __restrict__ W, int which) {
    float* __restrict__ C = which ? g_Pp : g_Qp;
    const int N = HID, K = DIN;
    __shared__ __align__(16) float As[16][68];
    __shared__ __align__(16) float Bs[16][68];
    int tid = threadIdx.x;
    int row0 = blockIdx.y * 64;
    int col0 = blockIdx.x * 64;
    int lm = tid >> 2;
    int lk = (tid & 3) << 2;
    int ty = tid >> 4;
    int tx = tid & 15;
    float acc[4][4] = {};
    const float* Ap = A + (size_t)(row0 + lm) * K + lk;
    const float* Wp = W + (size_t)(col0 + lm) * K + lk;
    for (int kt = 0; kt < K; kt += 16) {
        float4 a = *(const float4*)(Ap + kt);
        float4 b = *(const float4*)(Wp + kt);
        As[lk + 0][lm] = a.x; As[lk + 1][lm] = a.y; As[lk + 2][lm] = a.z; As[lk + 3][lm] = a.w;
        Bs[lk + 0][lm] = b.x; Bs[lk + 1][lm] = b.y; Bs[lk + 2][lm] = b.z; Bs[lk + 3][lm] = b.w;
        __syncthreads();
#pragma unroll
        for (int k = 0; k < 16; k++) {
            float4 av = *(const float4*)(&As[k][ty << 2]);
            float4 bv = *(const float4*)(&Bs[k][tx << 2]);
            float ar[4] = {av.x, av.y, av.z, av.w};
            float br[4] = {bv.x, bv.y, bv.z, bv.w};
#pragma unroll
            for (int mi = 0; mi < 4; mi++)
#pragma unroll
                for (int ni = 0; ni < 4; ni++)
                    acc[mi][ni] = fmaf(ar[mi], br[ni], acc[mi][ni]);
        }
        __syncthreads();
    }
#pragma unroll
    for (int mi = 0; mi < 4; mi++) {
        float4 o = make_float4(acc[mi][0], acc[mi][1], acc[mi][2], acc[mi][3]);
        *(float4*)(C + (size_t)(row0 + (ty << 2) + mi) * N + col0 + (tx << 2)) = o;
    }
}

// pad kernels: shift ncu's -s 5 -c 1 capture window onto rnn_persistent
__global__ void pad_kernel() {}

// ---------------- persistent recurrent kernel ----------------
// SMEM floats: s_qp 25600 | s_w1 2048 | s_w4 2048 | s_w5 3072 | s_vt 256 |
//   s_pi 256 | s_lh 256 | s_logit 128 | s_a 128 | s_hh 768  => 34560 floats
#define SMEM_FLOATS (25600 + 2048 + 2048 + 3072 + 256 + 256 + 256 + 128 + 128 + 768)
#define SMEM_BYTES  (SMEM_FLOATS * 4)

__global__ void __launch_bounds__(NTHR, 1) rnn_persistent(
    const float* __restrict__ vT,
    const float* __restrict__ WvP,
    const float* __restrict__ Wg,
    const float* __restrict__ W_ih,
    const float* __restrict__ W_hh,
    float* __restrict__ out) {
    extern __shared__ float sm[];
    float* s_qp    = sm;                       // [QLEN][HID]
    float* s_w1    = s_qp + QLEN * HID;        // 8 rows x HID  (WvP + W_hh shard)
    float* s_w4    = s_w1 + 8 * HID;           // 4 rows x H2   (Wg shard)
    float* s_w5    = s_w4 + 4 * H2;            // 6 rows x H2   (W_ih shard)
    float* s_vt    = s_w5 + 6 * H2;
    float* s_pi    = s_vt + HID;
    float* s_lh    = s_pi + HID;               // pi + lh during attention
    float* s_logit = s_lh + HID;
    float* s_a     = s_logit + 128;
    float* s_hh    = s_a + 128;                // [6][BATCH]: (g*2+j) x batch

    const int tid = threadIdx.x;
    const int b = blockIdx.x;   // batch owned for attention phase
    const int c = b;            // weight-shard id (h-dims 2c, 2c+1)

    unsigned tgt = *(volatile unsigned*)&g_gen;   // barrier base (pre-arrival)

    // ---- one-time SMEM loads ----
    for (int i = tid; i < 8 * HID; i += NTHR) {
        int r = i / HID, k = i - r * HID;
        const float* src;
        if (r < 2) src = WvP + (size_t)(2 * c + r) * HID;
        else {
            int g = (r - 2) >> 1, j = (r - 2) & 1;
            src = W_hh + (size_t)(g * HID + 2 * c + j) * HID;
        }
        s_w1[i] = src[k];
    }
    for (int i = tid; i < 4 * H2; i += NTHR) {
        int r = i / H2, k = i - r * H2;
        s_w4[i] = Wg[(size_t)(4 * c + r) * H2 + k];
    }
    for (int i = tid; i < 6 * H2; i += NTHR) {
        int r = i / H2, k = i - r * H2;
        int g = r >> 1, j = r & 1;
        s_w5[i] = W_ih[(size_t)(g * HID + 2 * c + j) * H2 + k];
    }
    for (int i = tid; i < HID; i += NTHR) s_vt[i] = vT[i];
    for (int i = tid; i < QLEN * HID; i += NTHR) {
        int q = i >> 8, h = i & 255;
        s_qp[i] = g_Qp[((size_t)q * BATCH + b) * HID + h];
    }
    if (tid < BATCH) {
        g_prev[tid * HID + 2 * c]     = 0.f;
        g_prev[tid * HID + 2 * c + 1] = 0.f;
    }
    grid_bar(++tgt);  // prev zeroed + precompute outputs coherently visible

    const int wrp = tid >> 5;
    const int lane = tid & 31;

#pragma unroll 1
    for (int step = 0; step < PLEN; step++) {
        // ---- P1: lh dims {2c,2c+1} -> g_lh ; hh gate triples -> s_hh
        {
            float acc[8][2];
            ws_dot<8, HID, 2, 8>(g_prev, s_w1, tid, acc);
            if ((tid & 7) == 0) {
                int b0 = (tid >> 3) * 2;
#pragma unroll
                for (int jb = 0; jb < 2; jb++) {
#pragma unroll
                    for (int j = 0; j < 2; j++)
                        g_lh[(b0 + jb) * HID + 2 * c + j] = acc[j][jb];
#pragma unroll
                    for (int r = 2; r < 8; r++)
                        s_hh[(r - 2) * BATCH + b0 + jb] = acc[r][jb];
                }
            }
        }
        grid_bar(++tgt);  // bar A: lh visible

        // ---- P2/P3: attention for batch b -> utct
        {
            if (tid < HID) {
                float piv = g_Pp[((size_t)step * BATCH + b) * HID + tid];
                s_pi[tid] = piv;
                s_lh[tid] = piv + __ldcg(&g_lh[b * HID + tid]);   // pi + lh
            }
            __syncthreads();
            for (int q = wrp; q < QLEN; q += 16) {
                const float* qp = s_qp + q * HID;
                float sum = 0.f;
#pragma unroll
                for (int ii = 0; ii < 8; ii++) {
                    int h = lane + (ii << 5);
                    float t = fast_tanh(s_lh[h] + qp[h]);
                    sum = fmaf(s_vt[h], t, sum);
                }
#pragma unroll
                for (int off = 16; off; off >>= 1)
                    sum += __shfl_xor_sync(0xffffffffu, sum, off);
                if (lane == 0) s_logit[q] = sum;
            }
            __syncthreads();
            if (wrp == 0) {
                float mx = -3.0e38f;
                for (int q = lane; q < QLEN; q += 32) mx = fmaxf(mx, s_logit[q]);
#pragma unroll
                for (int off = 16; off; off >>= 1)
                    mx = fmaxf(mx, __shfl_xor_sync(0xffffffffu, mx, off));
                float sum = 0.f;
                for (int q = lane; q < QLEN; q += 32) {
                    float e = __expf(s_logit[q] - mx);
                    s_a[q] = e;
                    sum += e;
                }
#pragma unroll
                for (int off = 16; off; off >>= 1)
                    sum += __shfl_xor_sync(0xffffffffu, sum, off);
                float rinv = __fdividef(1.f, sum);
                for (int q = lane; q < QLEN; q += 32) s_a[q] *= rinv;
            }
            __syncthreads();
            if (tid < HID) {
                float ct = 0.f;
                const float* qc = s_qp + tid;
#pragma unroll 4
                for (int q = 0; q < QLEN; q++) ct = fmaf(s_a[q], qc[q * HID], ct);
                g_utct[b * H2 + tid]       = s_pi[tid];
                g_utct[b * H2 + HID + tid] = ct;
            }
        }
        grid_bar(++tgt);  // bar B: utct visible

        // ---- P4: x = utct * sig(utct @ Wg^T), rows {4c..4c+4)
        {
            float acc[4][4];
            ws_dot<4, H2, 4, 16>(g_utct, s_w4, tid, acc);
            if ((tid & 15) == 0) {
                int b0 = (tid >> 4) * 4;
                int j0 = c * 4;
#pragma unroll
                for (int r = 0; r < 4; r++)
#pragma unroll
                    for (int jb = 0; jb < 4; jb++) {
                        float u = __ldcg(&g_utct[(b0 + jb) * H2 + j0 + r]);
                        g_x[(b0 + jb) * H2 + j0 + r] = u * fast_sig(acc[r][jb]);
                    }
            }
        }
        grid_bar(++tgt);  // bar C: x visible

        // ---- P5 + GRU update: gi = x @ W_ih^T (owned rows), fuse update
        {
            float acc[6][4];
            ws_dot<6, H2, 4, 16>(g_x, s_w5, tid, acc);
            if ((tid & 15) == 0) {
                int b0 = (tid >> 4) * 4;
#pragma unroll
                for (int j = 0; j < 2; j++)
#pragma unroll
                    for (int jb = 0; jb < 4; jb++) {
                        int d = 2 * c + j;
                        int bb = b0 + jb;
                        float hr = s_hh[(0 + j) * BATCH + bb];
                        float hz = s_hh[(2 + j) * BATCH + bb];
                        float hn = s_hh[(4 + j) * BATCH + bb];
                        float r = fast_sig(acc[j][jb]     + hr);
                        float z = fast_sig(acc[2 + j][jb] + hz);
                        float n = fast_tanh(acc[4 + j][jb] + r * hn);
                        float pv = __ldcg(&g_prev[bb * HID + d]);
                        float h = n + z * (pv - n);
                        g_prev[bb * HID + d] = h;
                        out[((size_t)step * BATCH + bb) * HID + d] = h;
                    }
            }
        }
        grid_bar(++tgt);  // bar D: prev visible for next P1
    }
}

// ---------------- launch ----------------
extern "C" void kernel_launch(void* const* d_in, const int* in_sizes, int n_in,
                              void* d_out, int out_size) {
    const float* passage_repr  = (const float*)d_in[0];   // [1000,128,512]
    const float* question_repr = (const float*)d_in[1];   // [100,128,512]
    // d_in[2], d_in[3]: masks, unused (faithful to reference)
    const float* vT   = (const float*)d_in[4];            // [256]
    const float* WuQ  = (const float*)d_in[5];            // [256,512]
    const float* WuP  = (const float*)d_in[6];            // [256,512]
    const float* WvP  = (const float*)d_in[7];            // [256,256]
    const float* Wg   = (const float*)d_in[8];            // [512,512]
    const float* W_ih = (const float*)d_in[9];            // [768,512]
    const float* W_hh = (const float*)d_in[10];           // [768,256]
    float* out = (float*)d_out;

    // align ncu's skip-5/capture-1 window onto rnn_persistent (launch index 5)
    pad_kernel<<<1, 32>>>();
    pad_kernel<<<1, 32>>>();
    pad_kernel<<<1, 32>>>();

    gemm_nt_kernel<<<dim3(HID / 64, (QLEN * BATCH) / 64), 256>>>(question_repr, WuQ, 0);
    gemm_nt_kernel<<<dim3(HID / 64, (PLEN * BATCH) / 64), 256>>>(passage_repr, WuP, 1);

    cudaFuncSetAttribute(rnn_persistent,
                         cudaFuncAttributeMaxDynamicSharedMemorySize, SMEM_BYTES);
    rnn_persistent<<<NBLK, NTHR, SMEM_BYTES>>>(vT, WvP, Wg, W_ih, W_hh, out);
}